// round 7
// baseline (speedup 1.0000x reference)
#include <cuda_runtime.h>
#include <cuda_bf16.h>
#include <cstdint>
#include <math.h>

#define B_   4
#define S_   1024
#define D_   512
#define V_   8192
#define NTOT (B_*S_)

// ------------------------- scratch (__device__ globals) -------------------------
__device__ float g_P [NTOT*D_];          // tanh(emb)
__device__ float g_C [NTOT*D_];          // cos(phases)
__device__ float g_Sn[NTOT*D_];          // sin(phases)
__device__ float g_feat[NTOT*2*D_];      // [cos(emb-cmean) | lc]  row stride 1024
__device__ float g_Wbig[2*D_*D_];        // [W_ctx@Wf2 ; Wf3]
__device__ float g_Ws5[5*D_];            // W_scale @ Wf0
__device__ float g_wsem[D_];             // W_sem @ Wf1
__device__ float g_biasc[D_];            // combined bias
__device__ float g_msc[NTOT*5];
__device__ float g_Dm[NTOT*9];           // raw band dots
__device__ float g_Dn[NTOT*9];           // normalized band dots
__device__ float g_sem[S_];
__device__ float g_cpart[B_*64*D_];
__device__ float g_cmean[B_*D_];
__device__ float g_y[NTOT*D_];
__device__ float g_x[NTOT*D_];
__device__ float g_t[NTOT*D_];
__device__ float g_h[NTOT*D_];

__device__ __forceinline__ float gelu_exact(float x){
    return 0.5f*x*(1.f + erff(x*0.70710678118654752440f));
}

__device__ __forceinline__ float blockReduceSum(float v){
    __shared__ float sh[8];
    int lane = threadIdx.x & 31, w = threadIdx.x >> 5;
    int nw = blockDim.x >> 5;
    __syncthreads();                 // protect sh reuse across calls
    #pragma unroll
    for (int o = 16; o; o >>= 1) v += __shfl_down_sync(0xffffffffu, v, o);
    if (lane == 0) sh[w] = v;
    __syncthreads();
    if (w == 0){
        v = (lane < nw) ? sh[lane] : 0.f;
        #pragma unroll
        for (int o = 16; o; o >>= 1) v += __shfl_down_sync(0xffffffffu, v, o);
        if (lane == 0) sh[0] = v;
    }
    __syncthreads();
    return sh[0];
}

// ------------------------- tf32 helpers -------------------------
__device__ __forceinline__ float to_tf32(float x){
    unsigned int o;
    asm("cvt.rna.tf32.f32 %0, %1;" : "=r"(o) : "f"(x));
    return __uint_as_float(o);
}
__device__ __forceinline__ void mma_tf32(float* d, const float* a, const float* b){
    asm volatile(
      "mma.sync.aligned.m16n8k8.row.col.f32.tf32.tf32.f32 "
      "{%0,%1,%2,%3}, {%4,%5,%6,%7}, {%8,%9}, {%0,%1,%2,%3};\n"
      : "+f"(d[0]), "+f"(d[1]), "+f"(d[2]), "+f"(d[3])
      : "r"(__float_as_uint(a[0])), "r"(__float_as_uint(a[1])),
        "r"(__float_as_uint(a[2])), "r"(__float_as_uint(a[3])),
        "r"(__float_as_uint(b[0])), "r"(__float_as_uint(b[1])));
}

// ------------------------- weight folding -------------------------
__global__ void foldw_kernel(const float* __restrict__ W_scale, const float* __restrict__ W_sem,
                             const float* __restrict__ b_scale, const float* __restrict__ b_sem,
                             const float* __restrict__ b_ctx,   const float* __restrict__ b_fuse,
                             const float* __restrict__ W_fuse)
{
    int c = threadIdx.x;          // 0..511
    int wb = blockIdx.x;          // 0..6
    if (wb < 5){
        float acc = 0.f;
        for (int d = 0; d < D_; d++)
            acc += W_scale[wb*D_ + d] * W_fuse[(size_t)d*D_ + c];
        g_Ws5[wb*D_ + c] = acc;
    } else if (wb == 5){
        float acc = 0.f;
        for (int d = 0; d < D_; d++)
            acc += W_sem[d] * W_fuse[(size_t)(D_ + d)*D_ + c];
        g_wsem[c] = acc;
    } else {
        float acc = b_fuse[c];
        for (int d = 0; d < D_; d++){
            acc += b_scale[d] * W_fuse[(size_t)d*D_ + c];
            acc += b_sem  [d] * W_fuse[(size_t)(D_ + d)*D_ + c];
            acc += b_ctx  [d] * W_fuse[(size_t)(2*D_ + d)*D_ + c];
        }
        g_biasc[c] = acc;
    }
}

// ------------------------- tf32 tensor-core GEMM -------------------------
// C[M,N] = A[M,K] @ B[K,N] (+bias). 128x128 block, BK=16, 256 threads (8 warps),
// warp tile 64x32 = 4x4 of m16n8k8. Both smem tiles use stride 136 floats
// (136 mod 32 == 8) -> all fragment LDS patterns hit 32 distinct banks.
__global__ void __launch_bounds__(256) gemm_tf32_kernel(
    const float* __restrict__ A, const float* __restrict__ B,
    const float* __restrict__ bias, float* __restrict__ C,
    int M, int N, int K)
{
    __shared__ __align__(16) float As[16][136];   // [k][m]
    __shared__ __align__(16) float Bs[16][136];   // [k][n]
    int tid = threadIdx.x;
    int bm = blockIdx.y*128, bn = blockIdx.x*128;
    int wid = tid >> 5, lane = tid & 31;
    int wm = (wid >> 2)*64;        // 0 / 64
    int wn = (wid & 3)*32;         // 0/32/64/96
    int lg = lane >> 2;            // groupID 0..7
    int lt = lane & 3;             // threadID_in_group 0..3

    float acc[4][4][4];
    #pragma unroll
    for (int i = 0; i < 4; i++)
        #pragma unroll
        for (int j = 0; j < 4; j++)
            #pragma unroll
            for (int r = 0; r < 4; r++) acc[i][j][r] = 0.f;

    int arow = tid >> 1;
    int acol = (tid & 1) * 8;
    const float* Aptr = A + (size_t)(bm + arow)*K + acol;
    int bk0 = tid >> 5;            // 0..7 (rows bk0 and bk0+8)
    int bnv = (tid & 31) * 4;
    const float* Bptr = B + (size_t)bk0*N + bn + bnv;

    for (int kt = 0; kt < K; kt += 16){
        float4 a0 = *(const float4*)(Aptr + kt);
        float4 a1 = *(const float4*)(Aptr + kt + 4);
        float4 b0 = *(const float4*)(Bptr + (size_t)kt*N);
        float4 b1 = *(const float4*)(Bptr + (size_t)(kt+8)*N);
        As[acol+0][arow] = to_tf32(a0.x); As[acol+1][arow] = to_tf32(a0.y);
        As[acol+2][arow] = to_tf32(a0.z); As[acol+3][arow] = to_tf32(a0.w);
        As[acol+4][arow] = to_tf32(a1.x); As[acol+5][arow] = to_tf32(a1.y);
        As[acol+6][arow] = to_tf32(a1.z); As[acol+7][arow] = to_tf32(a1.w);
        b0.x = to_tf32(b0.x); b0.y = to_tf32(b0.y); b0.z = to_tf32(b0.z); b0.w = to_tf32(b0.w);
        b1.x = to_tf32(b1.x); b1.y = to_tf32(b1.y); b1.z = to_tf32(b1.z); b1.w = to_tf32(b1.w);
        *(float4*)&Bs[bk0  ][bnv] = b0;
        *(float4*)&Bs[bk0+8][bnv] = b1;
        __syncthreads();

        #pragma unroll
        for (int ks = 0; ks < 16; ks += 8){
            float afr[4][4];
            #pragma unroll
            for (int mt = 0; mt < 4; mt++){
                int m0 = wm + mt*16;
                afr[mt][0] = As[ks+lt  ][m0+lg  ];
                afr[mt][1] = As[ks+lt  ][m0+8+lg];
                afr[mt][2] = As[ks+lt+4][m0+lg  ];
                afr[mt][3] = As[ks+lt+4][m0+8+lg];
            }
            float bfr[4][2];
            #pragma unroll
            for (int nt = 0; nt < 4; nt++){
                int n0 = wn + nt*8;
                bfr[nt][0] = Bs[ks+lt  ][n0+lg];
                bfr[nt][1] = Bs[ks+lt+4][n0+lg];
            }
            #pragma unroll
            for (int mt = 0; mt < 4; mt++)
                #pragma unroll
                for (int nt = 0; nt < 4; nt++)
                    mma_tf32(acc[mt][nt], afr[mt], bfr[nt]);
        }
        __syncthreads();
    }

    // epilogue: c0/c1 at (row, 2*lt), (row, 2*lt+1); c2/c3 at row+8
    #pragma unroll
    for (int mt = 0; mt < 4; mt++){
        int r = bm + wm + mt*16 + lg;
        #pragma unroll
        for (int nt = 0; nt < 4; nt++){
            int c = bn + wn + nt*8 + lt*2;
            float bv0 = bias ? bias[c]   : 0.f;
            float bv1 = bias ? bias[c+1] : 0.f;
            float2 o0 = make_float2(acc[mt][nt][0]+bv0, acc[mt][nt][1]+bv1);
            float2 o1 = make_float2(acc[mt][nt][2]+bv0, acc[mt][nt][3]+bv1);
            *(float2*)(C + (size_t)r*N + c)     = o0;
            *(float2*)(C + (size_t)(r+8)*N + c) = o1;
        }
    }
}

// ------------------------- phases + local coherence -------------------------
__global__ void phase_kernel(const float* __restrict__ emb){
    size_t i = (size_t)blockIdx.x*256 + threadIdx.x;   // over NTOT*D_
    float e = emb[i];
    float p = tanhf(e);
    float sp, cp; __sincosf(p, &sp, &cp);
    g_P[i] = p; g_C[i] = cp; g_Sn[i] = sp;
    size_t n = i >> 9; int d = (int)(i & 511);
    int t = (int)(n & (S_-1));
    float lc = (t < S_-1) ? cosf(emb[i + D_] - e) : 0.f;
    g_feat[n*(2*D_) + D_ + d] = lc;
}

// ------------------------- context mean -------------------------
__global__ void cmean_part_kernel(const float* __restrict__ emb, const float* __restrict__ mask){
    int ch = blockIdx.x, b = blockIdx.y;   // 64 chunks of 16 rows
    int t0 = ch*16;
    for (int d = threadIdx.x; d < D_; d += 256){
        float s = 0.f;
        for (int t = t0; t < t0+16; t++)
            s += emb[((size_t)(b*S_ + t))*D_ + d] * mask[b*S_ + t];
        g_cpart[(b*64+ch)*D_ + d] = s;
    }
}
__global__ void cmean_final_kernel(){
    int b = blockIdx.x, d = threadIdx.x;
    float s = 0.f;
    for (int c = 0; c < 64; c++) s += g_cpart[(b*64+c)*D_ + d];
    g_cmean[b*D_ + d] = s * (1.f/S_);
}
__global__ void ctxfeat_kernel(const float* __restrict__ emb){
    size_t i = (size_t)blockIdx.x*256 + threadIdx.x;   // over NTOT*D_
    size_t n = i >> 9; int d = (int)(i & 511);
    int b = (int)(n >> 10);
    g_feat[n*(2*D_) + d] = cosf(emb[i] - g_cmean[b*D_ + d]);
}

// ------------------------- banded token-similarity Gram -------------------------
__global__ void band_kernel(const float* __restrict__ tsm, const int* __restrict__ tok){
    __shared__ float Rs[24][136];
    __shared__ const float* rows[24];
    int b = blockIdx.y, i0 = blockIdx.x*16;
    int tid = threadIdx.x;                 // 192 threads
    if (tid < 24){
        int pos = min(i0 + tid, S_-1);
        rows[tid] = tsm + (size_t)tok[b*S_ + pos]*V_;
    }
    __syncthreads();
    int di = tid/9, de = tid%9;            // tid<144 valid pairs
    float acc = 0.f;
    for (int v0 = 0; v0 < V_; v0 += 128){
        #pragma unroll
        for (int l = tid; l < 24*32; l += 192){
            int r = l >> 5, cv = l & 31;
            *(float4*)&Rs[r][cv*4] = *(const float4*)(rows[r] + v0 + cv*4);
        }
        __syncthreads();
        if (tid < 144){
            int s2 = di + de;
            #pragma unroll 8
            for (int c = 0; c < 32; c++){
                float4 a  = *(float4*)&Rs[di][c*4];
                float4 bb = *(float4*)&Rs[s2][c*4];
                acc += a.x*bb.x + a.y*bb.y + a.z*bb.z + a.w*bb.w;
            }
        }
        __syncthreads();
    }
    if (tid < 144)
        g_Dm[((size_t)(b*S_ + i0 + di))*9 + de] = acc;
}

__global__ void bandnorm_kernel(){
    int n = blockIdx.x*256 + threadIdx.x;  // over NTOT
    int b = n >> 10, i = n & (S_-1);
    float ni = fmaxf(sqrtf(g_Dm[(size_t)n*9]), 1e-12f);
    for (int de = 0; de < 9; de++){
        int j = min(i + de, S_-1);
        float nj = fmaxf(sqrtf(g_Dm[((size_t)(b*S_ + j))*9]), 1e-12f);
        g_Dn[(size_t)n*9 + de] = g_Dm[(size_t)n*9 + de] / (ni*nj);
    }
}

// ------------------------- semantic coherence -------------------------
__global__ void sem_kernel(){
    int i = blockIdx.x;                    // 0..S-1
    int tid = threadIdx.x;                 // 256
    float acc = 0.f;
    for (int b = 0; b < B_; b++){
        const float* Pi = g_P + ((size_t)(b*S_ + i))*D_;
        for (int k = 0; k < 17; k++){
            int j = i - 8 + k;
            if (j < 0 || j >= S_) continue;
            int lo = min(i, j), de = abs(i - j);
            float w = g_Dn[((size_t)(b*S_ + lo))*9 + de];
            const float* Pj = g_P + ((size_t)(b*S_ + j))*D_;
            float s = 0.f;
            for (int d = tid; d < D_; d += 256)
                s += __cosf((Pi[d] - Pj[d]) * w);
            acc += s;
        }
    }
    acc = blockReduceSum(acc);
    if (tid == 0){
        int lo = max(0, i-8), hi = min(S_-1, i+8);
        float counts = (float)(hi - lo + 1);
        g_sem[i] = acc / ((float)B_ * counts * (float)D_);
    }
}

// ------------------------- multi-scale coherence -------------------------
__global__ void mscale_kernel(){
    __shared__ float Ps[80][33], Cs[80][33], Ss[80][33];
    __shared__ float red[256*5];
    int b = blockIdx.y, t0 = blockIdx.x*64;
    int tid = threadIdx.x;                 // 256
    int tl = tid & 63, dg = tid >> 6;      // 64 t-slots x 4 d-groups
    float acc[5] = {0.f,0.f,0.f,0.f,0.f};
    for (int d0 = 0; d0 < D_; d0 += 32){
        for (int l = tid; l < 80*32; l += 256){
            int r = l >> 5, dc = l & 31;
            int gt = t0 + r;
            float p = 0.f, c = 0.f, s = 0.f;
            if (gt < S_){
                size_t idx = ((size_t)(b*S_ + gt))*D_ + d0 + dc;
                p = g_P[idx]; c = g_C[idx]; s = g_Sn[idx];
            }
            Ps[r][dc] = p; Cs[r][dc] = c; Ss[r][dc] = s;
        }
        __syncthreads();
        for (int dd = 0; dd < 8; dd++){
            int dc = dg*8 + dd;
            float sp = 0.f, sc = 0.f, ss = 0.f;
            #pragma unroll
            for (int r = 0; r < 16; r++){
                sp += Ps[tl+r][dc]; sc += Cs[tl+r][dc]; ss += Ss[tl+r][dc];
                if (r==0 || r==1 || r==3 || r==7 || r==15){
                    int sidx = (r==0)?0:(r==1)?1:(r==3)?2:(r==7)?3:4;
                    float inv = 1.f/(float)(r+1);
                    float wm = sp*inv;
                    float sv, cv; __sincosf(wm, &sv, &cv);
                    acc[sidx] += cv*(sc*inv) + sv*(ss*inv);
                }
            }
        }
        __syncthreads();
    }
    #pragma unroll
    for (int s = 0; s < 5; s++) red[tid*5 + s] = acc[s];
    __syncthreads();
    if (dg == 0){
        int t = t0 + tl;
        #pragma unroll
        for (int s5 = 0; s5 < 5; s5++){
            float v = red[tl*5+s5] + red[(tl+64)*5+s5]
                    + red[(tl+128)*5+s5] + red[(tl+192)*5+s5];
            int sv = 1 << s5;
            g_msc[((size_t)(b*S_ + t))*5 + s5] = (t + sv <= S_) ? v*(1.f/D_) : 0.f;
        }
    }
}

// ------------------------- fuse epilogue + LN1 + GELU -------------------------
__global__ void fuse_ln1_kernel(const float* __restrict__ g1, const float* __restrict__ b1){
    int n = blockIdx.x;                    // 0..NTOT-1
    int tid = threadIdx.x;                 // 128
    int t = n & (S_-1);
    float sem = g_sem[t];
    float m0 = g_msc[(size_t)n*5+0], m1 = g_msc[(size_t)n*5+1], m2 = g_msc[(size_t)n*5+2];
    float m3 = g_msc[(size_t)n*5+3], m4 = g_msc[(size_t)n*5+4];
    float v[4]; float s = 0.f;
    #pragma unroll
    for (int j = 0; j < 4; j++){
        int c = tid + 128*j;
        float x = g_y[(size_t)n*D_ + c] + g_biasc[c] + sem*g_wsem[c]
                + m0*g_Ws5[c] + m1*g_Ws5[D_+c] + m2*g_Ws5[2*D_+c]
                + m3*g_Ws5[3*D_+c] + m4*g_Ws5[4*D_+c];
        v[j] = x; s += x;
    }
    float mean = blockReduceSum(s) * (1.f/D_);
    float q = 0.f;
    #pragma unroll
    for (int j = 0; j < 4; j++){ float d = v[j]-mean; q += d*d; }
    float var = blockReduceSum(q) * (1.f/D_);
    float rstd = rsqrtf(var + 1e-5f);
    #pragma unroll
    for (int j = 0; j < 4; j++){
        int c = tid + 128*j;
        float h = (v[j]-mean)*rstd*g1[c] + b1[c];
        g_x[(size_t)n*D_ + c] = gelu_exact(h);
    }
}

// ------------------------- plain LayerNorm -------------------------
__global__ void ln_plain_kernel(const float* __restrict__ src, const float* __restrict__ g,
                                const float* __restrict__ b, float* __restrict__ dst){
    int n = blockIdx.x; int tid = threadIdx.x;      // 128
    const float* r = src + (size_t)n*D_;
    float v[4]; float s = 0.f;
    #pragma unroll
    for (int j = 0; j < 4; j++){ v[j] = r[tid + 128*j]; s += v[j]; }
    float mean = blockReduceSum(s) * (1.f/D_);
    float q = 0.f;
    #pragma unroll
    for (int j = 0; j < 4; j++){ float d = v[j]-mean; q += d*d; }
    float var = blockReduceSum(q) * (1.f/D_);
    float rstd = rsqrtf(var + 1e-5f);
    #pragma unroll
    for (int j = 0; j < 4; j++){
        int c = tid + 128*j;
        dst[(size_t)n*D_ + c] = (v[j]-mean)*rstd*g[c] + b[c];
    }
}

// ------------------------- fused residual + LayerNorm -------------------------
// x += 0.1*gelu(h); dst = LN(x)
__global__ void resid_ln_kernel(const float* __restrict__ h, const float* __restrict__ g,
                                const float* __restrict__ b, float* __restrict__ dst){
    int n = blockIdx.x; int tid = threadIdx.x;      // 128
    float v[4]; float s = 0.f;
    #pragma unroll
    for (int j = 0; j < 4; j++){
        int c = tid + 128*j;
        float x = g_x[(size_t)n*D_ + c] + 0.1f*gelu_exact(h[(size_t)n*D_ + c]);
        g_x[(size_t)n*D_ + c] = x;
        v[j] = x; s += x;
    }
    float mean = blockReduceSum(s) * (1.f/D_);
    float q = 0.f;
    #pragma unroll
    for (int j = 0; j < 4; j++){ float d = v[j]-mean; q += d*d; }
    float var = blockReduceSum(q) * (1.f/D_);
    float rstd = rsqrtf(var + 1e-5f);
    #pragma unroll
    for (int j = 0; j < 4; j++){
        int c = tid + 128*j;
        dst[(size_t)n*D_ + c] = (v[j]-mean)*rstd*g[c] + b[c];
    }
}

// ------------------------- launch -------------------------
extern "C" void kernel_launch(void* const* d_in, const int* in_sizes, int n_in,
                              void* d_out, int out_size){
    (void)in_sizes; (void)n_in; (void)out_size;
    const float* emb     = (const float*)d_in[0];
    const int*   tok     = (const int*)  d_in[1];
    const float* mask    = (const float*)d_in[2];
    const float* tsm     = (const float*)d_in[3];
    const float* W_scale = (const float*)d_in[4];
    const float* b_scale = (const float*)d_in[5];
    const float* W_sem   = (const float*)d_in[6];
    const float* b_sem   = (const float*)d_in[7];
    const float* W_ctx   = (const float*)d_in[8];
    const float* b_ctx   = (const float*)d_in[9];
    const float* W_fuse  = (const float*)d_in[10];
    const float* b_fuse  = (const float*)d_in[11];
    const float* ln1g = (const float*)d_in[12]; const float* ln1b = (const float*)d_in[13];
    const float* ln2g = (const float*)d_in[14]; const float* ln2b = (const float*)d_in[15];
    const float* ln3g = (const float*)d_in[16]; const float* ln3b = (const float*)d_in[17];
    const float* We[3] = {(const float*)d_in[18], (const float*)d_in[20], (const float*)d_in[22]};
    const float* be[3] = {(const float*)d_in[19], (const float*)d_in[21], (const float*)d_in[23]};
    float* out = (float*)d_out;

    float *pWbig, *pFeat, *pY, *pX, *pT, *pH;
    cudaGetSymbolAddress((void**)&pWbig, g_Wbig);
    cudaGetSymbolAddress((void**)&pFeat, g_feat);
    cudaGetSymbolAddress((void**)&pY,    g_y);
    cudaGetSymbolAddress((void**)&pX,    g_x);
    cudaGetSymbolAddress((void**)&pT,    g_t);
    cudaGetSymbolAddress((void**)&pH,    g_h);

    // weight folding
    foldw_kernel<<<7, 512>>>(W_scale, W_sem, b_scale, b_sem, b_ctx, b_fuse, W_fuse);
    gemm_tf32_kernel<<<dim3(4,4), 256>>>(W_ctx, W_fuse + (size_t)2*D_*D_, nullptr, pWbig,
                                         D_, D_, D_);
    cudaMemcpyAsync(pWbig + D_*D_, W_fuse + (size_t)3*D_*D_,
                    (size_t)D_*D_*sizeof(float), cudaMemcpyDeviceToDevice);

    // features
    phase_kernel  <<<NTOT*D_/256, 256>>>(emb);
    cmean_part_kernel <<<dim3(64, B_), 256>>>(emb, mask);
    cmean_final_kernel<<<B_, 512>>>();
    ctxfeat_kernel<<<NTOT*D_/256, 256>>>(emb);

    // banded similarity + sem
    band_kernel    <<<dim3(S_/16, B_), 192>>>(tsm, tok);
    bandnorm_kernel<<<NTOT/256, 256>>>();
    sem_kernel     <<<S_, 256>>>();

    // multi-scale coherence
    mscale_kernel<<<dim3(S_/64, B_), 256>>>();

    // fused projection
    gemm_tf32_kernel<<<dim3(4,32), 256>>>(pFeat, pWbig, nullptr, pY, NTOT, D_, 2*D_);
    fuse_ln1_kernel<<<NTOT, 128>>>(ln1g, ln1b);

    // residual blocks (resid fused into following LN)
    ln_plain_kernel<<<NTOT, 128>>>(pX, ln2g, ln2b, pT);
    for (int l = 0; l < 3; l++){
        gemm_tf32_kernel<<<dim3(4,32), 256>>>(pT, We[l], be[l], pH, NTOT, D_, D_);
        if (l < 2) resid_ln_kernel<<<NTOT, 128>>>(pH, ln2g, ln2b, pT);
        else       resid_ln_kernel<<<NTOT, 128>>>(pH, ln3g, ln3b, out);
    }
}

// round 9
// speedup vs baseline: 1.1134x; 1.1134x over previous
#include <cuda_runtime.h>
#include <cuda_bf16.h>
#include <cstdint>
#include <math.h>

#define B_   4
#define S_   1024
#define D_   512
#define V_   8192
#define NTOT (B_*S_)

// ------------------------- scratch (__device__ globals) -------------------------
__device__ float g_P [NTOT*D_];          // tanh(emb)
__device__ float g_C [NTOT*D_];          // cos(phases)
__device__ float g_Sn[NTOT*D_];          // sin(phases)
__device__ float g_feat[NTOT*2*D_];      // [cos(emb-cmean) | lc]  row stride 1024
__device__ float g_Wbig[2*D_*D_];        // [W_ctx@Wf2 ; Wf3]
__device__ float g_Ws5[5*D_];            // W_scale @ Wf0
__device__ float g_wsem[D_];             // W_sem @ Wf1
__device__ float g_biasc[D_];            // combined bias
__device__ float g_msc[NTOT*5];
__device__ float g_Dm[NTOT*9];           // raw band dots
__device__ float g_Dn[NTOT*9];           // normalized band dots
__device__ float g_sem[S_];
__device__ float g_cpart[B_*64*D_];
__device__ float g_cmean[B_*D_];
__device__ float g_y[NTOT*D_];
__device__ float g_x[NTOT*D_];
__device__ float g_t[NTOT*D_];
__device__ float g_h[NTOT*D_];

__device__ __forceinline__ float gelu_exact(float x){
    return 0.5f*x*(1.f + erff(x*0.70710678118654752440f));
}

__device__ __forceinline__ float blockReduceSum(float v){
    __shared__ float sh[8];
    int lane = threadIdx.x & 31, w = threadIdx.x >> 5;
    int nw = blockDim.x >> 5;
    __syncthreads();
    #pragma unroll
    for (int o = 16; o; o >>= 1) v += __shfl_down_sync(0xffffffffu, v, o);
    if (lane == 0) sh[w] = v;
    __syncthreads();
    if (w == 0){
        v = (lane < nw) ? sh[lane] : 0.f;
        #pragma unroll
        for (int o = 16; o; o >>= 1) v += __shfl_down_sync(0xffffffffu, v, o);
        if (lane == 0) sh[0] = v;
    }
    __syncthreads();
    return sh[0];
}

// ------------------------- weight folding -------------------------
__global__ void foldw_kernel(const float* __restrict__ W_scale, const float* __restrict__ W_sem,
                             const float* __restrict__ b_scale, const float* __restrict__ b_sem,
                             const float* __restrict__ b_ctx,   const float* __restrict__ b_fuse,
                             const float* __restrict__ W_fuse)
{
    int c = threadIdx.x;          // 0..511
    int wb = blockIdx.x;          // 0..6
    if (wb < 5){
        float acc = 0.f;
        for (int d = 0; d < D_; d++)
            acc += W_scale[wb*D_ + d] * W_fuse[(size_t)d*D_ + c];
        g_Ws5[wb*D_ + c] = acc;
    } else if (wb == 5){
        float acc = 0.f;
        for (int d = 0; d < D_; d++)
            acc += W_sem[d] * W_fuse[(size_t)(D_ + d)*D_ + c];
        g_wsem[c] = acc;
    } else {
        float acc = b_fuse[c];
        for (int d = 0; d < D_; d++){
            acc += b_scale[d] * W_fuse[(size_t)d*D_ + c];
            acc += b_sem  [d] * W_fuse[(size_t)(D_ + d)*D_ + c];
            acc += b_ctx  [d] * W_fuse[(size_t)(2*D_ + d)*D_ + c];
        }
        g_biasc[c] = acc;
    }
}

// ------------------------- SGEMM with packed f32x2 FMA -------------------------
// C[M,N] = A[M,K] @ B[K,N] (+bias). 128x128 block tile, BK=16, 256 threads,
// 8x8 micro-tile computed as 8 broadcast-packs x 4 packed-pair FMA2.
__global__ void __launch_bounds__(256) sgemm_kernel(
    const float* __restrict__ A, const float* __restrict__ B,
    const float* __restrict__ bias, float* __restrict__ C,
    int M, int N, int K)
{
    __shared__ __align__(16) float As[16][136];    // [k][m], padded
    __shared__ __align__(16) float Bs[16][136];    // [k][n], padded (same stride)
    int tid = threadIdx.x;
    int bm = blockIdx.y*128, bn = blockIdx.x*128;
    int tx = tid & 15, ty = tid >> 4;
    int tm = ty*8, tn = tx*8;

    unsigned long long accp[8][4];
    #pragma unroll
    for (int i = 0; i < 8; i++)
        #pragma unroll
        for (int p = 0; p < 4; p++) accp[i][p] = 0ull;

    int arow = tid >> 1;
    int acol = (tid & 1) * 8;
    const float* Aptr = A + (size_t)(bm + arow)*K + acol;
    int bk0 = tid >> 5;              // 0..7 (rows bk0 and bk0+8)
    int bnv = (tid & 31) * 4;
    const float* Bptr = B + (size_t)bk0*N + bn + bnv;

    for (int kt = 0; kt < K; kt += 16){
        float4 a0 = *(const float4*)(Aptr + kt);
        float4 a1 = *(const float4*)(Aptr + kt + 4);
        float4 b0 = *(const float4*)(Bptr + (size_t)kt*N);
        float4 b1 = *(const float4*)(Bptr + (size_t)(kt+8)*N);
        As[acol+0][arow] = a0.x; As[acol+1][arow] = a0.y;
        As[acol+2][arow] = a0.z; As[acol+3][arow] = a0.w;
        As[acol+4][arow] = a1.x; As[acol+5][arow] = a1.y;
        As[acol+6][arow] = a1.z; As[acol+7][arow] = a1.w;
        *(float4*)&Bs[bk0  ][bnv] = b0;
        *(float4*)&Bs[bk0+8][bnv] = b1;
        __syncthreads();
        #pragma unroll
        for (int k = 0; k < 16; k++){
            float4 av0 = *(float4*)&As[k][tm];
            float4 av1 = *(float4*)&As[k][tm+4];
            ulonglong2 bq0 = *(ulonglong2*)&Bs[k][tn];
            ulonglong2 bq1 = *(ulonglong2*)&Bs[k][tn+4];
            unsigned long long b2[4] = {bq0.x, bq0.y, bq1.x, bq1.y};
            float a8[8] = {av0.x,av0.y,av0.z,av0.w,av1.x,av1.y,av1.z,av1.w};
            #pragma unroll
            for (int i = 0; i < 8; i++){
                unsigned long long a2;
                unsigned int ab = __float_as_uint(a8[i]);
                asm("mov.b64 %0, {%1, %1};" : "=l"(a2) : "r"(ab));
                #pragma unroll
                for (int p = 0; p < 4; p++)
                    asm("fma.rn.f32x2 %0, %1, %2, %0;"
                        : "+l"(accp[i][p]) : "l"(a2), "l"(b2[p]));
            }
        }
        __syncthreads();
    }

    float bv[8];
    #pragma unroll
    for (int j = 0; j < 8; j++) bv[j] = bias ? bias[bn+tn+j] : 0.f;
    #pragma unroll
    for (int i = 0; i < 8; i++){
        float o[8];
        #pragma unroll
        for (int p = 0; p < 4; p++){
            unsigned int lo, hi;
            asm("mov.b64 {%0, %1}, %2;" : "=r"(lo), "=r"(hi) : "l"(accp[i][p]));
            o[2*p]   = __uint_as_float(lo) + bv[2*p];
            o[2*p+1] = __uint_as_float(hi) + bv[2*p+1];
        }
        float* cp = C + (size_t)(bm+tm+i)*N + bn + tn;
        *(float4*)cp     = make_float4(o[0], o[1], o[2], o[3]);
        *(float4*)(cp+4) = make_float4(o[4], o[5], o[6], o[7]);
    }
}

// ------------------------- phases + local coherence -------------------------
__global__ void phase_kernel(const float* __restrict__ emb){
    size_t i = (size_t)blockIdx.x*256 + threadIdx.x;   // over NTOT*D_
    float e = emb[i];
    float p = tanhf(e);
    float sp, cp; __sincosf(p, &sp, &cp);
    g_P[i] = p; g_C[i] = cp; g_Sn[i] = sp;
    size_t n = i >> 9; int d = (int)(i & 511);
    int t = (int)(n & (S_-1));
    float lc = (t < S_-1) ? cosf(emb[i + D_] - e) : 0.f;
    g_feat[n*(2*D_) + D_ + d] = lc;
}

// ------------------------- context mean -------------------------
__global__ void cmean_part_kernel(const float* __restrict__ emb, const float* __restrict__ mask){
    int ch = blockIdx.x, b = blockIdx.y;   // 64 chunks of 16 rows
    int t0 = ch*16;
    for (int d = threadIdx.x; d < D_; d += 256){
        float s = 0.f;
        for (int t = t0; t < t0+16; t++)
            s += emb[((size_t)(b*S_ + t))*D_ + d] * mask[b*S_ + t];
        g_cpart[(b*64+ch)*D_ + d] = s;
    }
}
__global__ void cmean_final_kernel(){
    int b = blockIdx.x, d = threadIdx.x;
    float s = 0.f;
    for (int c = 0; c < 64; c++) s += g_cpart[(b*64+c)*D_ + d];
    g_cmean[b*D_ + d] = s * (1.f/S_);
}
__global__ void ctxfeat_kernel(const float* __restrict__ emb){
    size_t i = (size_t)blockIdx.x*256 + threadIdx.x;   // over NTOT*D_
    size_t n = i >> 9; int d = (int)(i & 511);
    int b = (int)(n >> 10);
    g_feat[n*(2*D_) + d] = cosf(emb[i] - g_cmean[b*D_ + d]);
}

// ------------------------- banded token-similarity Gram -------------------------
__global__ void band_kernel(const float* __restrict__ tsm, const int* __restrict__ tok){
    __shared__ float Rs[24][136];
    __shared__ const float* rows[24];
    int b = blockIdx.y, i0 = blockIdx.x*16;
    int tid = threadIdx.x;                 // 192 threads
    if (tid < 24){
        int pos = min(i0 + tid, S_-1);
        rows[tid] = tsm + (size_t)tok[b*S_ + pos]*V_;
    }
    __syncthreads();
    int di = tid/9, de = tid%9;            // tid<144 valid pairs
    float acc = 0.f;
    for (int v0 = 0; v0 < V_; v0 += 128){
        #pragma unroll
        for (int l = tid; l < 24*32; l += 192){
            int r = l >> 5, cv = l & 31;
            *(float4*)&Rs[r][cv*4] = *(const float4*)(rows[r] + v0 + cv*4);
        }
        __syncthreads();
        if (tid < 144){
            int s2 = di + de;
            #pragma unroll 8
            for (int c = 0; c < 32; c++){
                float4 a  = *(float4*)&Rs[di][c*4];
                float4 bb = *(float4*)&Rs[s2][c*4];
                acc += a.x*bb.x + a.y*bb.y + a.z*bb.z + a.w*bb.w;
            }
        }
        __syncthreads();
    }
    if (tid < 144)
        g_Dm[((size_t)(b*S_ + i0 + di))*9 + de] = acc;
}

__global__ void bandnorm_kernel(){
    int n = blockIdx.x*256 + threadIdx.x;  // over NTOT
    int b = n >> 10, i = n & (S_-1);
    float ni = fmaxf(sqrtf(g_Dm[(size_t)n*9]), 1e-12f);
    for (int de = 0; de < 9; de++){
        int j = min(i + de, S_-1);
        float nj = fmaxf(sqrtf(g_Dm[((size_t)(b*S_ + j))*9]), 1e-12f);
        g_Dn[(size_t)n*9 + de] = g_Dm[(size_t)n*9 + de] / (ni*nj);
    }
}

// ------------------------- semantic coherence -------------------------
__global__ void sem_kernel(){
    int i = blockIdx.x;                    // 0..S-1
    int tid = threadIdx.x;                 // 256
    float acc = 0.f;
    for (int b = 0; b < B_; b++){
        const float* Pi = g_P + ((size_t)(b*S_ + i))*D_;
        for (int k = 0; k < 17; k++){
            int j = i - 8 + k;
            if (j < 0 || j >= S_) continue;
            int lo = min(i, j), de = abs(i - j);
            float w = g_Dn[((size_t)(b*S_ + lo))*9 + de];
            const float* Pj = g_P + ((size_t)(b*S_ + j))*D_;
            float s = 0.f;
            for (int d = tid; d < D_; d += 256)
                s += __cosf((Pi[d] - Pj[d]) * w);
            acc += s;
        }
    }
    acc = blockReduceSum(acc);
    if (tid == 0){
        int lo = max(0, i-8), hi = min(S_-1, i+8);
        float counts = (float)(hi - lo + 1);
        g_sem[i] = acc / ((float)B_ * counts * (float)D_);
    }
}

// ------------------------- multi-scale coherence -------------------------
__global__ void mscale_kernel(){
    __shared__ float Ps[80][33], Cs[80][33], Ss[80][33];
    __shared__ float red[256*5];
    int b = blockIdx.y, t0 = blockIdx.x*64;
    int tid = threadIdx.x;                 // 256
    int tl = tid & 63, dg = tid >> 6;      // 64 t-slots x 4 d-groups
    float acc[5] = {0.f,0.f,0.f,0.f,0.f};
    for (int d0 = 0; d0 < D_; d0 += 32){
        for (int l = tid; l < 80*32; l += 256){
            int r = l >> 5, dc = l & 31;
            int gt = t0 + r;
            float p = 0.f, c = 0.f, s = 0.f;
            if (gt < S_){
                size_t idx = ((size_t)(b*S_ + gt))*D_ + d0 + dc;
                p = g_P[idx]; c = g_C[idx]; s = g_Sn[idx];
            }
            Ps[r][dc] = p; Cs[r][dc] = c; Ss[r][dc] = s;
        }
        __syncthreads();
        for (int dd = 0; dd < 8; dd++){
            int dc = dg*8 + dd;
            float sp = 0.f, sc = 0.f, ss = 0.f;
            #pragma unroll
            for (int r = 0; r < 16; r++){
                sp += Ps[tl+r][dc]; sc += Cs[tl+r][dc]; ss += Ss[tl+r][dc];
                if (r==0 || r==1 || r==3 || r==7 || r==15){
                    int sidx = (r==0)?0:(r==1)?1:(r==3)?2:(r==7)?3:4;
                    float inv = 1.f/(float)(r+1);
                    float wm = sp*inv;
                    float sv, cv; __sincosf(wm, &sv, &cv);
                    acc[sidx] += cv*(sc*inv) + sv*(ss*inv);
                }
            }
        }
        __syncthreads();
    }
    #pragma unroll
    for (int s = 0; s < 5; s++) red[tid*5 + s] = acc[s];
    __syncthreads();
    if (dg == 0){
        int t = t0 + tl;
        #pragma unroll
        for (int s5 = 0; s5 < 5; s5++){
            float v = red[tl*5+s5] + red[(tl+64)*5+s5]
                    + red[(tl+128)*5+s5] + red[(tl+192)*5+s5];
            int sv = 1 << s5;
            g_msc[((size_t)(b*S_ + t))*5 + s5] = (t + sv <= S_) ? v*(1.f/D_) : 0.f;
        }
    }
}

// ------------------------- fuse epilogue + LN1 + GELU -------------------------
__global__ void fuse_ln1_kernel(const float* __restrict__ g1, const float* __restrict__ b1){
    int n = blockIdx.x;                    // 0..NTOT-1
    int tid = threadIdx.x;                 // 128
    int t = n & (S_-1);
    float sem = g_sem[t];
    float m0 = g_msc[(size_t)n*5+0], m1 = g_msc[(size_t)n*5+1], m2 = g_msc[(size_t)n*5+2];
    float m3 = g_msc[(size_t)n*5+3], m4 = g_msc[(size_t)n*5+4];
    float v[4]; float s = 0.f;
    #pragma unroll
    for (int j = 0; j < 4; j++){
        int c = tid + 128*j;
        float x = g_y[(size_t)n*D_ + c] + g_biasc[c] + sem*g_wsem[c]
                + m0*g_Ws5[c] + m1*g_Ws5[D_+c] + m2*g_Ws5[2*D_+c]
                + m3*g_Ws5[3*D_+c] + m4*g_Ws5[4*D_+c];
        v[j] = x; s += x;
    }
    float mean = blockReduceSum(s) * (1.f/D_);
    float q = 0.f;
    #pragma unroll
    for (int j = 0; j < 4; j++){ float d = v[j]-mean; q += d*d; }
    float var = blockReduceSum(q) * (1.f/D_);
    float rstd = rsqrtf(var + 1e-5f);
    #pragma unroll
    for (int j = 0; j < 4; j++){
        int c = tid + 128*j;
        float h = (v[j]-mean)*rstd*g1[c] + b1[c];
        g_x[(size_t)n*D_ + c] = gelu_exact(h);
    }
}

// ------------------------- plain LayerNorm -------------------------
__global__ void ln_plain_kernel(const float* __restrict__ src, const float* __restrict__ g,
                                const float* __restrict__ b, float* __restrict__ dst){
    int n = blockIdx.x; int tid = threadIdx.x;      // 128
    const float* r = src + (size_t)n*D_;
    float v[4]; float s = 0.f;
    #pragma unroll
    for (int j = 0; j < 4; j++){ v[j] = r[tid + 128*j]; s += v[j]; }
    float mean = blockReduceSum(s) * (1.f/D_);
    float q = 0.f;
    #pragma unroll
    for (int j = 0; j < 4; j++){ float d = v[j]-mean; q += d*d; }
    float var = blockReduceSum(q) * (1.f/D_);
    float rstd = rsqrtf(var + 1e-5f);
    #pragma unroll
    for (int j = 0; j < 4; j++){
        int c = tid + 128*j;
        dst[(size_t)n*D_ + c] = (v[j]-mean)*rstd*g[c] + b[c];
    }
}

// ------------------------- fused residual + LayerNorm -------------------------
// x += 0.1*gelu(h); dst = LN(x)
__global__ void resid_ln_kernel(const float* __restrict__ h, const float* __restrict__ g,
                                const float* __restrict__ b, float* __restrict__ dst){
    int n = blockIdx.x; int tid = threadIdx.x;      // 128
    float v[4]; float s = 0.f;
    #pragma unroll
    for (int j = 0; j < 4; j++){
        int c = tid + 128*j;
        float x = g_x[(size_t)n*D_ + c] + 0.1f*gelu_exact(h[(size_t)n*D_ + c]);
        g_x[(size_t)n*D_ + c] = x;
        v[j] = x; s += x;
    }
    float mean = blockReduceSum(s) * (1.f/D_);
    float q = 0.f;
    #pragma unroll
    for (int j = 0; j < 4; j++){ float d = v[j]-mean; q += d*d; }
    float var = blockReduceSum(q) * (1.f/D_);
    float rstd = rsqrtf(var + 1e-5f);
    #pragma unroll
    for (int j = 0; j < 4; j++){
        int c = tid + 128*j;
        dst[(size_t)n*D_ + c] = (v[j]-mean)*rstd*g[c] + b[c];
    }
}

// ------------------------- launch -------------------------
extern "C" void kernel_launch(void* const* d_in, const int* in_sizes, int n_in,
                              void* d_out, int out_size){
    (void)in_sizes; (void)n_in; (void)out_size;
    const float* emb     = (const float*)d_in[0];
    const int*   tok     = (const int*)  d_in[1];
    const float* mask    = (const float*)d_in[2];
    const float* tsm     = (const float*)d_in[3];
    const float* W_scale = (const float*)d_in[4];
    const float* b_scale = (const float*)d_in[5];
    const float* W_sem   = (const float*)d_in[6];
    const float* b_sem   = (const float*)d_in[7];
    const float* W_ctx   = (const float*)d_in[8];
    const float* b_ctx   = (const float*)d_in[9];
    const float* W_fuse  = (const float*)d_in[10];
    const float* b_fuse  = (const float*)d_in[11];
    const float* ln1g = (const float*)d_in[12]; const float* ln1b = (const float*)d_in[13];
    const float* ln2g = (const float*)d_in[14]; const float* ln2b = (const float*)d_in[15];
    const float* ln3g = (const float*)d_in[16]; const float* ln3b = (const float*)d_in[17];
    const float* We[3] = {(const float*)d_in[18], (const float*)d_in[20], (const float*)d_in[22]};
    const float* be[3] = {(const float*)d_in[19], (const float*)d_in[21], (const float*)d_in[23]};
    float* out = (float*)d_out;

    float *pWbig, *pFeat, *pY, *pX, *pT, *pH;
    cudaGetSymbolAddress((void**)&pWbig, g_Wbig);
    cudaGetSymbolAddress((void**)&pFeat, g_feat);
    cudaGetSymbolAddress((void**)&pY,    g_y);
    cudaGetSymbolAddress((void**)&pX,    g_x);
    cudaGetSymbolAddress((void**)&pT,    g_t);
    cudaGetSymbolAddress((void**)&pH,    g_h);

    // weight folding
    foldw_kernel<<<7, 512>>>(W_scale, W_sem, b_scale, b_sem, b_ctx, b_fuse, W_fuse);
    sgemm_kernel<<<dim3(4,4), 256>>>(W_ctx, W_fuse + (size_t)2*D_*D_, nullptr, pWbig,
                                     D_, D_, D_);
    cudaMemcpyAsync(pWbig + D_*D_, W_fuse + (size_t)3*D_*D_,
                    (size_t)D_*D_*sizeof(float), cudaMemcpyDeviceToDevice);

    // features
    phase_kernel  <<<NTOT*D_/256, 256>>>(emb);
    cmean_part_kernel <<<dim3(64, B_), 256>>>(emb, mask);
    cmean_final_kernel<<<B_, 512>>>();
    ctxfeat_kernel<<<NTOT*D_/256, 256>>>(emb);

    // banded similarity + sem
    band_kernel    <<<dim3(S_/16, B_), 192>>>(tsm, tok);
    bandnorm_kernel<<<NTOT/256, 256>>>();
    sem_kernel     <<<S_, 256>>>();

    // multi-scale coherence
    mscale_kernel<<<dim3(S_/64, B_), 256>>>();

    // fused projection
    sgemm_kernel<<<dim3(4,32), 256>>>(pFeat, pWbig, nullptr, pY, NTOT, D_, 2*D_);
    fuse_ln1_kernel<<<NTOT, 128>>>(ln1g, ln1b);

    // residual blocks (resid fused into following LN)
    ln_plain_kernel<<<NTOT, 128>>>(pX, ln2g, ln2b, pT);
    for (int l = 0; l < 3; l++){
        sgemm_kernel<<<dim3(4,32), 256>>>(pT, We[l], be[l], pH, NTOT, D_, D_);
        if (l < 2) resid_ln_kernel<<<NTOT, 128>>>(pH, ln2g, ln2b, pT);
        else       resid_ln_kernel<<<NTOT, 128>>>(pH, ln3g, ln3b, out);
    }
}

// round 12
// speedup vs baseline: 1.2012x; 1.0788x over previous
#include <cuda_runtime.h>
#include <cuda_bf16.h>
#include <cstdint>
#include <math.h>

#define B_   4
#define S_   1024
#define D_   512
#define V_   8192
#define NTOT (B_*S_)

// ------------------------- scratch (__device__ globals) -------------------------
__device__ float g_P [NTOT*D_];          // tanh(emb)
__device__ float g_C [NTOT*D_];          // cos(phases)
__device__ float g_Sn[NTOT*D_];          // sin(phases)
__device__ float g_feat[NTOT*2*D_];      // [cos(emb-cmean) | lc]  row stride 1024
__device__ float g_Wbig[2*D_*D_];        // [W_ctx@Wf2 ; Wf3]
__device__ float g_Ws5[5*D_];            // W_scale @ Wf0
__device__ float g_wsem[D_];             // W_sem @ Wf1
__device__ float g_biasc[D_];            // combined bias
__device__ float g_msc[NTOT*5];
__device__ float g_Dm[NTOT*9];           // raw band dots
__device__ float g_Dn[NTOT*9];           // normalized band dots
__device__ float g_sem[S_];
__device__ float g_cpart[B_*64*D_];
__device__ float g_cmean[B_*D_];
__device__ float g_y[NTOT*D_];
__device__ float g_x[NTOT*D_];
__device__ float g_t[NTOT*D_];
__device__ float g_h[NTOT*D_];

__device__ __forceinline__ float gelu_exact(float x){
    return 0.5f*x*(1.f + erff(x*0.70710678118654752440f));
}

// cos via Taylor-12, valid |x| <= ~2.2 (abs err < 2e-7)
__device__ __forceinline__ float cos_poly(float x){
    float x2 = x*x;
    float r =  2.0876757e-9f;
    r = fmaf(r, x2, -2.7557319e-7f);
    r = fmaf(r, x2,  2.4801587e-5f);
    r = fmaf(r, x2, -1.3888889e-3f);
    r = fmaf(r, x2,  4.1666667e-2f);
    r = fmaf(r, x2, -0.5f);
    r = fmaf(r, x2,  1.0f);
    return r;
}
// sin via Taylor-9, valid |x| <= ~1.2 (abs err < 3e-8)
__device__ __forceinline__ float sin_poly(float x){
    float x2 = x*x;
    float r =  2.7557319e-6f;
    r = fmaf(r, x2, -1.9841270e-4f);
    r = fmaf(r, x2,  8.3333333e-3f);
    r = fmaf(r, x2, -1.6666667e-1f);
    r = fmaf(r, x2,  1.0f);
    return r * x;
}

__device__ __forceinline__ float blockReduceSum(float v){
    __shared__ float sh[8];
    int lane = threadIdx.x & 31, w = threadIdx.x >> 5;
    int nw = blockDim.x >> 5;
    __syncthreads();
    #pragma unroll
    for (int o = 16; o; o >>= 1) v += __shfl_down_sync(0xffffffffu, v, o);
    if (lane == 0) sh[w] = v;
    __syncthreads();
    if (w == 0){
        v = (lane < nw) ? sh[lane] : 0.f;
        #pragma unroll
        for (int o = 16; o; o >>= 1) v += __shfl_down_sync(0xffffffffu, v, o);
        if (lane == 0) sh[0] = v;
    }
    __syncthreads();
    return sh[0];
}

// ------------------------- weight folding -------------------------
__global__ void foldw_kernel(const float* __restrict__ W_scale, const float* __restrict__ W_sem,
                             const float* __restrict__ b_scale, const float* __restrict__ b_sem,
                             const float* __restrict__ b_ctx,   const float* __restrict__ b_fuse,
                             const float* __restrict__ W_fuse)
{
    int c = threadIdx.x;          // 0..511
    int wb = blockIdx.x;          // 0..6
    if (wb < 5){
        float acc = 0.f;
        for (int d = 0; d < D_; d++)
            acc += W_scale[wb*D_ + d] * W_fuse[(size_t)d*D_ + c];
        g_Ws5[wb*D_ + c] = acc;
    } else if (wb == 5){
        float acc = 0.f;
        for (int d = 0; d < D_; d++)
            acc += W_sem[d] * W_fuse[(size_t)(D_ + d)*D_ + c];
        g_wsem[c] = acc;
    } else {
        float acc = b_fuse[c];
        for (int d = 0; d < D_; d++){
            acc += b_scale[d] * W_fuse[(size_t)d*D_ + c];
            acc += b_sem  [d] * W_fuse[(size_t)(D_ + d)*D_ + c];
            acc += b_ctx  [d] * W_fuse[(size_t)(2*D_ + d)*D_ + c];
        }
        g_biasc[c] = acc;
    }
}

// ------------------------- SGEMM: f32x2 FMA + double-buffered smem -------------------------
// C[M,N] = A[M,K] @ B[K,N] (+bias). 128x128 block tile, BK=16, 256 threads.
__global__ void __launch_bounds__(256) sgemm_kernel(
    const float* __restrict__ A, const float* __restrict__ B,
    const float* __restrict__ bias, float* __restrict__ C,
    int M, int N, int K)
{
    __shared__ __align__(16) float As[2][16][136];
    __shared__ __align__(16) float Bs[2][16][136];
    int tid = threadIdx.x;
    int bm = blockIdx.y*128, bn = blockIdx.x*128;
    int tx = tid & 15, ty = tid >> 4;
    int tm = ty*8, tn = tx*8;

    unsigned long long accp[8][4];
    #pragma unroll
    for (int i = 0; i < 8; i++)
        #pragma unroll
        for (int p = 0; p < 4; p++) accp[i][p] = 0ull;

    int arow = tid >> 1;
    int acol = (tid & 1) * 8;
    const float* Aptr = A + (size_t)(bm + arow)*K + acol;
    int bk0 = tid >> 5;              // 0..7 (rows bk0 and bk0+8)
    int bnv = (tid & 31) * 4;
    const float* Bptr = B + (size_t)bk0*N + bn + bnv;

    // preload tile 0
    {
        float4 a0 = *(const float4*)(Aptr);
        float4 a1 = *(const float4*)(Aptr + 4);
        float4 b0 = *(const float4*)(Bptr);
        float4 b1 = *(const float4*)(Bptr + (size_t)8*N);
        As[0][acol+0][arow] = a0.x; As[0][acol+1][arow] = a0.y;
        As[0][acol+2][arow] = a0.z; As[0][acol+3][arow] = a0.w;
        As[0][acol+4][arow] = a1.x; As[0][acol+5][arow] = a1.y;
        As[0][acol+6][arow] = a1.z; As[0][acol+7][arow] = a1.w;
        *(float4*)&Bs[0][bk0  ][bnv] = b0;
        *(float4*)&Bs[0][bk0+8][bnv] = b1;
    }
    __syncthreads();

    int cur = 0;
    for (int kt = 0; kt < K; kt += 16){
        int nxt = cur ^ 1;
        bool more = (kt + 16 < K);
        float4 na0, na1, nb0, nb1;
        if (more){
            na0 = *(const float4*)(Aptr + kt + 16);
            na1 = *(const float4*)(Aptr + kt + 20);
            nb0 = *(const float4*)(Bptr + (size_t)(kt+16)*N);
            nb1 = *(const float4*)(Bptr + (size_t)(kt+24)*N);
        }
        #pragma unroll
        for (int k = 0; k < 16; k++){
            float4 av0 = *(float4*)&As[cur][k][tm];
            float4 av1 = *(float4*)&As[cur][k][tm+4];
            ulonglong2 bq0 = *(ulonglong2*)&Bs[cur][k][tn];
            ulonglong2 bq1 = *(ulonglong2*)&Bs[cur][k][tn+4];
            unsigned long long b2[4] = {bq0.x, bq0.y, bq1.x, bq1.y};
            float a8[8] = {av0.x,av0.y,av0.z,av0.w,av1.x,av1.y,av1.z,av1.w};
            #pragma unroll
            for (int i = 0; i < 8; i++){
                unsigned long long a2;
                unsigned int ab = __float_as_uint(a8[i]);
                asm("mov.b64 %0, {%1, %1};" : "=l"(a2) : "r"(ab));
                #pragma unroll
                for (int p = 0; p < 4; p++)
                    asm("fma.rn.f32x2 %0, %1, %2, %0;"
                        : "+l"(accp[i][p]) : "l"(a2), "l"(b2[p]));
            }
        }
        if (more){
            As[nxt][acol+0][arow] = na0.x; As[nxt][acol+1][arow] = na0.y;
            As[nxt][acol+2][arow] = na0.z; As[nxt][acol+3][arow] = na0.w;
            As[nxt][acol+4][arow] = na1.x; As[nxt][acol+5][arow] = na1.y;
            As[nxt][acol+6][arow] = na1.z; As[nxt][acol+7][arow] = na1.w;
            *(float4*)&Bs[nxt][bk0  ][bnv] = nb0;
            *(float4*)&Bs[nxt][bk0+8][bnv] = nb1;
        }
        __syncthreads();
        cur = nxt;
    }

    float bv[8];
    #pragma unroll
    for (int j = 0; j < 8; j++) bv[j] = bias ? bias[bn+tn+j] : 0.f;
    #pragma unroll
    for (int i = 0; i < 8; i++){
        float o[8];
        #pragma unroll
        for (int p = 0; p < 4; p++){
            unsigned int lo, hi;
            asm("mov.b64 {%0, %1}, %2;" : "=r"(lo), "=r"(hi) : "l"(accp[i][p]));
            o[2*p]   = __uint_as_float(lo) + bv[2*p];
            o[2*p+1] = __uint_as_float(hi) + bv[2*p+1];
        }
        float* cp = C + (size_t)(bm+tm+i)*N + bn + tn;
        *(float4*)cp     = make_float4(o[0], o[1], o[2], o[3]);
        *(float4*)(cp+4) = make_float4(o[4], o[5], o[6], o[7]);
    }
}

// ------------------------- phases + local coherence -------------------------
__global__ void phase_kernel(const float* __restrict__ emb){
    size_t i = (size_t)blockIdx.x*256 + threadIdx.x;   // over NTOT*D_
    float e = emb[i];
    float p = tanhf(e);
    g_P[i] = p; g_C[i] = cos_poly(p); g_Sn[i] = sin_poly(p);
    size_t n = i >> 9; int d = (int)(i & 511);
    int t = (int)(n & (S_-1));
    float lc = (t < S_-1) ? cosf(emb[i + D_] - e) : 0.f;
    g_feat[n*(2*D_) + D_ + d] = lc;
}

// ------------------------- context mean -------------------------
__global__ void cmean_part_kernel(const float* __restrict__ emb, const float* __restrict__ mask){
    int ch = blockIdx.x, b = blockIdx.y;   // 64 chunks of 16 rows
    int t0 = ch*16;
    for (int d = threadIdx.x; d < D_; d += 256){
        float s = 0.f;
        for (int t = t0; t < t0+16; t++)
            s += emb[((size_t)(b*S_ + t))*D_ + d] * mask[b*S_ + t];
        g_cpart[(b*64+ch)*D_ + d] = s;
    }
}
__global__ void cmean_final_kernel(){
    int b = blockIdx.x, d = threadIdx.x;
    float s = 0.f;
    for (int c = 0; c < 64; c++) s += g_cpart[(b*64+c)*D_ + d];
    g_cmean[b*D_ + d] = s * (1.f/S_);
}
__global__ void ctxfeat_kernel(const float* __restrict__ emb){
    size_t i = (size_t)blockIdx.x*256 + threadIdx.x;   // over NTOT*D_
    size_t n = i >> 9; int d = (int)(i & 511);
    int b = (int)(n >> 10);
    g_feat[n*(2*D_) + d] = cosf(emb[i] - g_cmean[b*D_ + d]);
}

// ------------------------- banded token-similarity Gram -------------------------
__global__ void band_kernel(const float* __restrict__ tsm, const int* __restrict__ tok){
    __shared__ float Rs[24][136];
    __shared__ const float* rows[24];
    int b = blockIdx.y, i0 = blockIdx.x*16;
    int tid = threadIdx.x;                 // 192 threads
    if (tid < 24){
        int pos = min(i0 + tid, S_-1);
        rows[tid] = tsm + (size_t)tok[b*S_ + pos]*V_;
    }
    __syncthreads();
    int di = tid/9, de = tid%9;            // tid<144 valid pairs
    float acc = 0.f;
    for (int v0 = 0; v0 < V_; v0 += 128){
        #pragma unroll
        for (int l = tid; l < 24*32; l += 192){
            int r = l >> 5, cv = l & 31;
            *(float4*)&Rs[r][cv*4] = *(const float4*)(rows[r] + v0 + cv*4);
        }
        __syncthreads();
        if (tid < 144){
            int s2 = di + de;
            #pragma unroll 8
            for (int c = 0; c < 32; c++){
                float4 a  = *(float4*)&Rs[di][c*4];
                float4 bb = *(float4*)&Rs[s2][c*4];
                acc += a.x*bb.x + a.y*bb.y + a.z*bb.z + a.w*bb.w;
            }
        }
        __syncthreads();
    }
    if (tid < 144)
        g_Dm[((size_t)(b*S_ + i0 + di))*9 + de] = acc;
}

__global__ void bandnorm_kernel(){
    int n = blockIdx.x*256 + threadIdx.x;  // over NTOT
    int b = n >> 10, i = n & (S_-1);
    float ni = fmaxf(sqrtf(g_Dm[(size_t)n*9]), 1e-12f);
    for (int de = 0; de < 9; de++){
        int j = min(i + de, S_-1);
        float nj = fmaxf(sqrtf(g_Dm[((size_t)(b*S_ + j))*9]), 1e-12f);
        g_Dn[(size_t)n*9 + de] = g_Dm[(size_t)n*9 + de] / (ni*nj);
    }
}

// ------------------------- semantic coherence (poly cos, float4) -------------------------
__global__ void sem_kernel(){
    __shared__ float wtab[4][17];
    int i = blockIdx.x;                    // 0..S-1
    int tid = threadIdx.x;                 // 128
    if (tid < 68){
        int b = tid / 17, k = tid % 17;
        int j = i - 8 + k;
        float w = 0.f;
        if (j >= 0 && j < S_){
            int lo = min(i, j), de = abs(i - j);
            w = g_Dn[((size_t)(b*S_ + lo))*9 + de];
        }
        wtab[b][k] = w;
    }
    __syncthreads();

    int d = tid * 4;
    int kmin = (i < 8) ? (8 - i) : 0;
    int kmax = (i > S_-9) ? (S_-1-i) + 8 : 16;
    float acc = 0.f;
    #pragma unroll
    for (int b = 0; b < B_; b++){
        float4 Pi4 = *(const float4*)(g_P + ((size_t)(b*S_ + i))*D_ + d);
        for (int k = kmin; k <= kmax; k++){
            int j = i - 8 + k;
            float w = wtab[b][k];
            float4 Pj4 = *(const float4*)(g_P + ((size_t)(b*S_ + j))*D_ + d);
            acc += cos_poly((Pi4.x - Pj4.x)*w);
            acc += cos_poly((Pi4.y - Pj4.y)*w);
            acc += cos_poly((Pi4.z - Pj4.z)*w);
            acc += cos_poly((Pi4.w - Pj4.w)*w);
        }
    }
    float tot = blockReduceSum(acc);
    if (tid == 0){
        float counts = (float)(kmax - kmin + 1);
        g_sem[i] = tot / ((float)B_ * counts * (float)D_);
    }
}

// ------------------------- multi-scale coherence (poly sincos) -------------------------
__global__ void mscale_kernel(){
    __shared__ float Ps[80][33], Cs[80][33], Ss[80][33];
    __shared__ float red[256*5];
    int b = blockIdx.y, t0 = blockIdx.x*64;
    int tid = threadIdx.x;                 // 256
    int tl = tid & 63, dg = tid >> 6;      // 64 t-slots x 4 d-groups
    float acc[5] = {0.f,0.f,0.f,0.f,0.f};
    for (int d0 = 0; d0 < D_; d0 += 32){
        for (int l = tid; l < 80*32; l += 256){
            int r = l >> 5, dc = l & 31;
            int gt = t0 + r;
            float p = 0.f, c = 0.f, s = 0.f;
            if (gt < S_){
                size_t idx = ((size_t)(b*S_ + gt))*D_ + d0 + dc;
                p = g_P[idx]; c = g_C[idx]; s = g_Sn[idx];
            }
            Ps[r][dc] = p; Cs[r][dc] = c; Ss[r][dc] = s;
        }
        __syncthreads();
        for (int dd = 0; dd < 8; dd++){
            int dc = dg*8 + dd;
            float sp = 0.f, sc = 0.f, ss = 0.f;
            #pragma unroll
            for (int r = 0; r < 16; r++){
                sp += Ps[tl+r][dc]; sc += Cs[tl+r][dc]; ss += Ss[tl+r][dc];
                if (r==0 || r==1 || r==3 || r==7 || r==15){
                    int sidx = (r==0)?0:(r==1)?1:(r==3)?2:(r==7)?3:4;
                    float inv = 1.f/(float)(r+1);
                    float wm = sp*inv;
                    acc[sidx] += cos_poly(wm)*(sc*inv) + sin_poly(wm)*(ss*inv);
                }
            }
        }
        __syncthreads();
    }
    #pragma unroll
    for (int s = 0; s < 5; s++) red[tid*5 + s] = acc[s];
    __syncthreads();
    if (dg == 0){
        int t = t0 + tl;
        #pragma unroll
        for (int s5 = 0; s5 < 5; s5++){
            float v = red[tl*5+s5] + red[(tl+64)*5+s5]
                    + red[(tl+128)*5+s5] + red[(tl+192)*5+s5];
            int sv = 1 << s5;
            g_msc[((size_t)(b*S_ + t))*5 + s5] = (t + sv <= S_) ? v*(1.f/D_) : 0.f;
        }
    }
}

// ------------------------- fuse epilogue + LN1 + GELU -------------------------
__global__ void fuse_ln1_kernel(const float* __restrict__ g1, const float* __restrict__ b1){
    int n = blockIdx.x;                    // 0..NTOT-1
    int tid = threadIdx.x;                 // 128
    int t = n & (S_-1);
    float sem = g_sem[t];
    float m0 = g_msc[(size_t)n*5+0], m1 = g_msc[(size_t)n*5+1], m2 = g_msc[(size_t)n*5+2];
    float m3 = g_msc[(size_t)n*5+3], m4 = g_msc[(size_t)n*5+4];
    float v[4]; float s = 0.f;
    #pragma unroll
    for (int j = 0; j < 4; j++){
        int c = tid + 128*j;
        float x = g_y[(size_t)n*D_ + c] + g_biasc[c] + sem*g_wsem[c]
                + m0*g_Ws5[c] + m1*g_Ws5[D_+c] + m2*g_Ws5[2*D_+c]
                + m3*g_Ws5[3*D_+c] + m4*g_Ws5[4*D_+c];
        v[j] = x; s += x;
    }
    float mean = blockReduceSum(s) * (1.f/D_);
    float q = 0.f;
    #pragma unroll
    for (int j = 0; j < 4; j++){ float d = v[j]-mean; q += d*d; }
    float var = blockReduceSum(q) * (1.f/D_);
    float rstd = rsqrtf(var + 1e-5f);
    #pragma unroll
    for (int j = 0; j < 4; j++){
        int c = tid + 128*j;
        float h = (v[j]-mean)*rstd*g1[c] + b1[c];
        g_x[(size_t)n*D_ + c] = gelu_exact(h);
    }
}

// ------------------------- plain LayerNorm -------------------------
__global__ void ln_plain_kernel(const float* __restrict__ src, const float* __restrict__ g,
                                const float* __restrict__ b, float* __restrict__ dst){
    int n = blockIdx.x; int tid = threadIdx.x;      // 128
    const float* r = src + (size_t)n*D_;
    float v[4]; float s = 0.f;
    #pragma unroll
    for (int j = 0; j < 4; j++){ v[j] = r[tid + 128*j]; s += v[j]; }
    float mean = blockReduceSum(s) * (1.f/D_);
    float q = 0.f;
    #pragma unroll
    for (int j = 0; j < 4; j++){ float d = v[j]-mean; q += d*d; }
    float var = blockReduceSum(q) * (1.f/D_);
    float rstd = rsqrtf(var + 1e-5f);
    #pragma unroll
    for (int j = 0; j < 4; j++){
        int c = tid + 128*j;
        dst[(size_t)n*D_ + c] = (v[j]-mean)*rstd*g[c] + b[c];
    }
}

// ------------------------- fused residual + LayerNorm -------------------------
// x += 0.1*gelu(h); dst = LN(x)
__global__ void resid_ln_kernel(const float* __restrict__ h, const float* __restrict__ g,
                                const float* __restrict__ b, float* __restrict__ dst){
    int n = blockIdx.x; int tid = threadIdx.x;      // 128
    float v[4]; float s = 0.f;
    #pragma unroll
    for (int j = 0; j < 4; j++){
        int c = tid + 128*j;
        float x = g_x[(size_t)n*D_ + c] + 0.1f*gelu_exact(h[(size_t)n*D_ + c]);
        g_x[(size_t)n*D_ + c] = x;
        v[j] = x; s += x;
    }
    float mean = blockReduceSum(s) * (1.f/D_);
    float q = 0.f;
    #pragma unroll
    for (int j = 0; j < 4; j++){ float d = v[j]-mean; q += d*d; }
    float var = blockReduceSum(q) * (1.f/D_);
    float rstd = rsqrtf(var + 1e-5f);
    #pragma unroll
    for (int j = 0; j < 4; j++){
        int c = tid + 128*j;
        dst[(size_t)n*D_ + c] = (v[j]-mean)*rstd*g[c] + b[c];
    }
}

// ------------------------- launch -------------------------
extern "C" void kernel_launch(void* const* d_in, const int* in_sizes, int n_in,
                              void* d_out, int out_size){
    (void)in_sizes; (void)n_in; (void)out_size;
    const float* emb     = (const float*)d_in[0];
    const int*   tok     = (const int*)  d_in[1];
    const float* mask    = (const float*)d_in[2];
    const float* tsm     = (const float*)d_in[3];
    const float* W_scale = (const float*)d_in[4];
    const float* b_scale = (const float*)d_in[5];
    const float* W_sem   = (const float*)d_in[6];
    const float* b_sem   = (const float*)d_in[7];
    const float* W_ctx   = (const float*)d_in[8];
    const float* b_ctx   = (const float*)d_in[9];
    const float* W_fuse  = (const float*)d_in[10];
    const float* b_fuse  = (const float*)d_in[11];
    const float* ln1g = (const float*)d_in[12]; const float* ln1b = (const float*)d_in[13];
    const float* ln2g = (const float*)d_in[14]; const float* ln2b = (const float*)d_in[15];
    const float* ln3g = (const float*)d_in[16]; const float* ln3b = (const float*)d_in[17];
    const float* We[3] = {(const float*)d_in[18], (const float*)d_in[20], (const float*)d_in[22]};
    const float* be[3] = {(const float*)d_in[19], (const float*)d_in[21], (const float*)d_in[23]};
    float* out = (float*)d_out;

    float *pWbig, *pFeat, *pY, *pX, *pT, *pH;
    cudaGetSymbolAddress((void**)&pWbig, g_Wbig);
    cudaGetSymbolAddress((void**)&pFeat, g_feat);
    cudaGetSymbolAddress((void**)&pY,    g_y);
    cudaGetSymbolAddress((void**)&pX,    g_x);
    cudaGetSymbolAddress((void**)&pT,    g_t);
    cudaGetSymbolAddress((void**)&pH,    g_h);

    // weight folding
    foldw_kernel<<<7, 512>>>(W_scale, W_sem, b_scale, b_sem, b_ctx, b_fuse, W_fuse);
    sgemm_kernel<<<dim3(4,4), 256>>>(W_ctx, W_fuse + (size_t)2*D_*D_, nullptr, pWbig,
                                     D_, D_, D_);
    cudaMemcpyAsync(pWbig + D_*D_, W_fuse + (size_t)3*D_*D_,
                    (size_t)D_*D_*sizeof(float), cudaMemcpyDeviceToDevice);

    // features
    phase_kernel  <<<NTOT*D_/256, 256>>>(emb);
    cmean_part_kernel <<<dim3(64, B_), 256>>>(emb, mask);
    cmean_final_kernel<<<B_, 512>>>();
    ctxfeat_kernel<<<NTOT*D_/256, 256>>>(emb);

    // banded similarity + sem
    band_kernel    <<<dim3(S_/16, B_), 192>>>(tsm, tok);
    bandnorm_kernel<<<NTOT/256, 256>>>();
    sem_kernel     <<<S_, 128>>>();

    // multi-scale coherence
    mscale_kernel<<<dim3(S_/64, B_), 256>>>();

    // fused projection
    sgemm_kernel<<<dim3(4,32), 256>>>(pFeat, pWbig, nullptr, pY, NTOT, D_, 2*D_);
    fuse_ln1_kernel<<<NTOT, 128>>>(ln1g, ln1b);

    // residual blocks (resid fused into following LN)
    ln_plain_kernel<<<NTOT, 128>>>(pX, ln2g, ln2b, pT);
    for (int l = 0; l < 3; l++){
        sgemm_kernel<<<dim3(4,32), 256>>>(pT, We[l], be[l], pH, NTOT, D_, D_);
        if (l < 2) resid_ln_kernel<<<NTOT, 128>>>(pH, ln2g, ln2b, pT);
        else       resid_ln_kernel<<<NTOT, 128>>>(pH, ln3g, ln3b, out);
    }
}

// round 13
// speedup vs baseline: 1.3794x; 1.1483x over previous
#include <cuda_runtime.h>
#include <cuda_bf16.h>
#include <cstdint>
#include <math.h>

#define B_   4
#define S_   1024
#define D_   512
#define V_   8192
#define NTOT (B_*S_)

// ------------------------- scratch (__device__ globals) -------------------------
__device__ float g_P [NTOT*D_];          // tanh(emb)
__device__ float g_C [NTOT*D_];          // cos(phases)
__device__ float g_Sn[NTOT*D_];          // sin(phases)
__device__ float g_feat[NTOT*2*D_];      // [cos(emb-cmean) | lc]  row stride 1024
__device__ float g_Wbig[2*D_*D_];        // [W_ctx@Wf2 ; Wf3]
__device__ float g_Ws5[5*D_];            // W_scale @ Wf0
__device__ float g_wsem[D_];             // W_sem @ Wf1
__device__ float g_biasc[D_];            // combined bias
__device__ float g_msc[NTOT*5];
__device__ float g_Dm[NTOT*9];           // raw band dots
__device__ float g_Dn[NTOT*9];           // normalized band dots
__device__ float g_sem[S_];
__device__ float g_cpart[B_*64*D_];
__device__ float g_cmean[B_*D_];
__device__ float g_y[NTOT*D_];
__device__ float g_x[NTOT*D_];
__device__ float g_t[NTOT*D_];
__device__ float g_h[NTOT*D_];

// fast tanh: (1 - e^{-2|x|})/(1 + e^{-2|x|}), abs err ~1e-7
__device__ __forceinline__ float tanh_fast(float x){
    float ax = fabsf(x);
    float t  = __expf(-2.f*ax);
    float r  = __fdividef(1.f - t, 1.f + t);
    return copysignf(r, x);
}

// gelu via Abramowitz-Stegun 7.1.26 erf (abs err 1.5e-7)
__device__ __forceinline__ float gelu_exact(float x){
    float u  = 0.70710678118654752440f * x;
    float au = fabsf(u);
    float t  = __fdividef(1.f, fmaf(0.3275911f, au, 1.f));
    float p  = 1.061405429f;
    p = fmaf(p, t, -1.453152027f);
    p = fmaf(p, t,  1.421413741f);
    p = fmaf(p, t, -0.284496736f);
    p = fmaf(p, t,  0.254829592f);
    p = p * t;
    float e  = __expf(-au*au);
    float erfa = 1.f - p*e;
    float erfu = copysignf(erfa, u);
    return 0.5f*x*(1.f + erfu);
}

// cos via Taylor-12, valid |x| <= ~2.2 (abs err < 2e-7)
__device__ __forceinline__ float cos_poly(float x){
    float x2 = x*x;
    float r =  2.0876757e-9f;
    r = fmaf(r, x2, -2.7557319e-7f);
    r = fmaf(r, x2,  2.4801587e-5f);
    r = fmaf(r, x2, -1.3888889e-3f);
    r = fmaf(r, x2,  4.1666667e-2f);
    r = fmaf(r, x2, -0.5f);
    r = fmaf(r, x2,  1.0f);
    return r;
}
// sin via Taylor-9, valid |x| <= ~1.2 (abs err < 3e-8)
__device__ __forceinline__ float sin_poly(float x){
    float x2 = x*x;
    float r =  2.7557319e-6f;
    r = fmaf(r, x2, -1.9841270e-4f);
    r = fmaf(r, x2,  8.3333333e-3f);
    r = fmaf(r, x2, -1.6666667e-1f);
    r = fmaf(r, x2,  1.0f);
    return r * x;
}

__device__ __forceinline__ float blockReduceSum(float v){
    __shared__ float sh[8];
    int lane = threadIdx.x & 31, w = threadIdx.x >> 5;
    int nw = blockDim.x >> 5;
    __syncthreads();
    #pragma unroll
    for (int o = 16; o; o >>= 1) v += __shfl_down_sync(0xffffffffu, v, o);
    if (lane == 0) sh[w] = v;
    __syncthreads();
    if (w == 0){
        v = (lane < nw) ? sh[lane] : 0.f;
        #pragma unroll
        for (int o = 16; o; o >>= 1) v += __shfl_down_sync(0xffffffffu, v, o);
        if (lane == 0) sh[0] = v;
    }
    __syncthreads();
    return sh[0];
}

// ------------------------- weight folding -------------------------
__global__ void foldw_kernel(const float* __restrict__ W_scale, const float* __restrict__ W_sem,
                             const float* __restrict__ b_scale, const float* __restrict__ b_sem,
                             const float* __restrict__ b_ctx,   const float* __restrict__ b_fuse,
                             const float* __restrict__ W_fuse)
{
    int c = threadIdx.x;          // 0..511
    int wb = blockIdx.x;          // 0..6
    if (wb < 5){
        float acc = 0.f;
        for (int d = 0; d < D_; d++)
            acc += W_scale[wb*D_ + d] * W_fuse[(size_t)d*D_ + c];
        g_Ws5[wb*D_ + c] = acc;
    } else if (wb == 5){
        float acc = 0.f;
        for (int d = 0; d < D_; d++)
            acc += W_sem[d] * W_fuse[(size_t)(D_ + d)*D_ + c];
        g_wsem[c] = acc;
    } else {
        float acc = b_fuse[c];
        for (int d = 0; d < D_; d++){
            acc += b_scale[d] * W_fuse[(size_t)d*D_ + c];
            acc += b_sem  [d] * W_fuse[(size_t)(D_ + d)*D_ + c];
            acc += b_ctx  [d] * W_fuse[(size_t)(2*D_ + d)*D_ + c];
        }
        g_biasc[c] = acc;
    }
}

// ------------------------- SGEMM: f32x2 FMA + double-buffered smem -------------------------
__global__ void __launch_bounds__(256) sgemm_kernel(
    const float* __restrict__ A, const float* __restrict__ B,
    const float* __restrict__ bias, float* __restrict__ C,
    int M, int N, int K)
{
    __shared__ __align__(16) float As[2][16][136];
    __shared__ __align__(16) float Bs[2][16][136];
    int tid = threadIdx.x;
    int bm = blockIdx.y*128, bn = blockIdx.x*128;
    int tx = tid & 15, ty = tid >> 4;
    int tm = ty*8, tn = tx*8;

    unsigned long long accp[8][4];
    #pragma unroll
    for (int i = 0; i < 8; i++)
        #pragma unroll
        for (int p = 0; p < 4; p++) accp[i][p] = 0ull;

    int arow = tid >> 1;
    int acol = (tid & 1) * 8;
    const float* Aptr = A + (size_t)(bm + arow)*K + acol;
    int bk0 = tid >> 5;
    int bnv = (tid & 31) * 4;
    const float* Bptr = B + (size_t)bk0*N + bn + bnv;

    {
        float4 a0 = *(const float4*)(Aptr);
        float4 a1 = *(const float4*)(Aptr + 4);
        float4 b0 = *(const float4*)(Bptr);
        float4 b1 = *(const float4*)(Bptr + (size_t)8*N);
        As[0][acol+0][arow] = a0.x; As[0][acol+1][arow] = a0.y;
        As[0][acol+2][arow] = a0.z; As[0][acol+3][arow] = a0.w;
        As[0][acol+4][arow] = a1.x; As[0][acol+5][arow] = a1.y;
        As[0][acol+6][arow] = a1.z; As[0][acol+7][arow] = a1.w;
        *(float4*)&Bs[0][bk0  ][bnv] = b0;
        *(float4*)&Bs[0][bk0+8][bnv] = b1;
    }
    __syncthreads();

    int cur = 0;
    for (int kt = 0; kt < K; kt += 16){
        int nxt = cur ^ 1;
        bool more = (kt + 16 < K);
        float4 na0, na1, nb0, nb1;
        if (more){
            na0 = *(const float4*)(Aptr + kt + 16);
            na1 = *(const float4*)(Aptr + kt + 20);
            nb0 = *(const float4*)(Bptr + (size_t)(kt+16)*N);
            nb1 = *(const float4*)(Bptr + (size_t)(kt+24)*N);
        }
        #pragma unroll
        for (int k = 0; k < 16; k++){
            float4 av0 = *(float4*)&As[cur][k][tm];
            float4 av1 = *(float4*)&As[cur][k][tm+4];
            ulonglong2 bq0 = *(ulonglong2*)&Bs[cur][k][tn];
            ulonglong2 bq1 = *(ulonglong2*)&Bs[cur][k][tn+4];
            unsigned long long b2[4] = {bq0.x, bq0.y, bq1.x, bq1.y};
            float a8[8] = {av0.x,av0.y,av0.z,av0.w,av1.x,av1.y,av1.z,av1.w};
            #pragma unroll
            for (int i = 0; i < 8; i++){
                unsigned long long a2;
                unsigned int ab = __float_as_uint(a8[i]);
                asm("mov.b64 %0, {%1, %1};" : "=l"(a2) : "r"(ab));
                #pragma unroll
                for (int p = 0; p < 4; p++)
                    asm("fma.rn.f32x2 %0, %1, %2, %0;"
                        : "+l"(accp[i][p]) : "l"(a2), "l"(b2[p]));
            }
        }
        if (more){
            As[nxt][acol+0][arow] = na0.x; As[nxt][acol+1][arow] = na0.y;
            As[nxt][acol+2][arow] = na0.z; As[nxt][acol+3][arow] = na0.w;
            As[nxt][acol+4][arow] = na1.x; As[nxt][acol+5][arow] = na1.y;
            As[nxt][acol+6][arow] = na1.z; As[nxt][acol+7][arow] = na1.w;
            *(float4*)&Bs[nxt][bk0  ][bnv] = nb0;
            *(float4*)&Bs[nxt][bk0+8][bnv] = nb1;
        }
        __syncthreads();
        cur = nxt;
    }

    float bv[8];
    #pragma unroll
    for (int j = 0; j < 8; j++) bv[j] = bias ? bias[bn+tn+j] : 0.f;
    #pragma unroll
    for (int i = 0; i < 8; i++){
        float o[8];
        #pragma unroll
        for (int p = 0; p < 4; p++){
            unsigned int lo, hi;
            asm("mov.b64 {%0, %1}, %2;" : "=r"(lo), "=r"(hi) : "l"(accp[i][p]));
            o[2*p]   = __uint_as_float(lo) + bv[2*p];
            o[2*p+1] = __uint_as_float(hi) + bv[2*p+1];
        }
        float* cp = C + (size_t)(bm+tm+i)*N + bn + tn;
        *(float4*)cp     = make_float4(o[0], o[1], o[2], o[3]);
        *(float4*)(cp+4) = make_float4(o[4], o[5], o[6], o[7]);
    }
}

// ------------------------- phases + local coherence -------------------------
__global__ void phase_kernel(const float* __restrict__ emb){
    size_t i = (size_t)blockIdx.x*256 + threadIdx.x;
    float e = emb[i];
    float p = tanh_fast(e);
    g_P[i] = p; g_C[i] = cos_poly(p); g_Sn[i] = sin_poly(p);
    size_t n = i >> 9; int d = (int)(i & 511);
    int t = (int)(n & (S_-1));
    float lc = (t < S_-1) ? __cosf(emb[i + D_] - e) : 0.f;
    g_feat[n*(2*D_) + D_ + d] = lc;
}

// ------------------------- context mean -------------------------
__global__ void cmean_part_kernel(const float* __restrict__ emb, const float* __restrict__ mask){
    int ch = blockIdx.x, b = blockIdx.y;
    int t0 = ch*16;
    for (int d = threadIdx.x; d < D_; d += 256){
        float s = 0.f;
        for (int t = t0; t < t0+16; t++)
            s += emb[((size_t)(b*S_ + t))*D_ + d] * mask[b*S_ + t];
        g_cpart[(b*64+ch)*D_ + d] = s;
    }
}
__global__ void cmean_final_kernel(){
    int b = blockIdx.x, d = threadIdx.x;
    float s = 0.f;
    for (int c = 0; c < 64; c++) s += g_cpart[(b*64+c)*D_ + d];
    g_cmean[b*D_ + d] = s * (1.f/S_);
}
__global__ void ctxfeat_kernel(const float* __restrict__ emb){
    size_t i = (size_t)blockIdx.x*256 + threadIdx.x;
    size_t n = i >> 9; int d = (int)(i & 511);
    int b = (int)(n >> 10);
    g_feat[n*(2*D_) + d] = __cosf(emb[i] - g_cmean[b*D_ + d]);
}

// ------------------------- banded token-similarity Gram (prefetched) -------------------------
__global__ void band_kernel(const float* __restrict__ tsm, const int* __restrict__ tok){
    __shared__ float Rs[24][136];
    __shared__ const float* rows[24];
    int b = blockIdx.y, i0 = blockIdx.x*16;
    int tid = threadIdx.x;                 // 192 threads
    if (tid < 24){
        int pos = min(i0 + tid, S_-1);
        rows[tid] = tsm + (size_t)tok[b*S_ + pos]*V_;
    }
    __syncthreads();
    int di = tid/9, de = tid%9;            // tid<144 valid pairs

    // prefetch chunk 0 into registers (768 float4 slots / 192 threads = 4 each)
    float4 pre[4];
    #pragma unroll
    for (int q = 0; q < 4; q++){
        int l = tid + q*192;
        int r = l >> 5, cv = l & 31;
        pre[q] = *(const float4*)(rows[r] + cv*4);
    }

    float acc = 0.f;
    for (int v0 = 0; v0 < V_; v0 += 128){
        #pragma unroll
        for (int q = 0; q < 4; q++){
            int l = tid + q*192;
            int r = l >> 5, cv = l & 31;
            *(float4*)&Rs[r][cv*4] = pre[q];
        }
        __syncthreads();
        if (v0 + 128 < V_){
            #pragma unroll
            for (int q = 0; q < 4; q++){
                int l = tid + q*192;
                int r = l >> 5, cv = l & 31;
                pre[q] = *(const float4*)(rows[r] + v0 + 128 + cv*4);
            }
        }
        if (tid < 144){
            int s2 = di + de;
            #pragma unroll 8
            for (int c = 0; c < 32; c++){
                float4 a  = *(float4*)&Rs[di][c*4];
                float4 bb = *(float4*)&Rs[s2][c*4];
                acc += a.x*bb.x + a.y*bb.y + a.z*bb.z + a.w*bb.w;
            }
        }
        __syncthreads();
    }
    if (tid < 144)
        g_Dm[((size_t)(b*S_ + i0 + di))*9 + de] = acc;
}

__global__ void bandnorm_kernel(){
    int n = blockIdx.x*256 + threadIdx.x;
    int b = n >> 10, i = n & (S_-1);
    float ni = fmaxf(sqrtf(g_Dm[(size_t)n*9]), 1e-12f);
    for (int de = 0; de < 9; de++){
        int j = min(i + de, S_-1);
        float nj = fmaxf(sqrtf(g_Dm[((size_t)(b*S_ + j))*9]), 1e-12f);
        g_Dn[(size_t)n*9 + de] = g_Dm[(size_t)n*9 + de] / (ni*nj);
    }
}

// ------------------------- semantic coherence (poly cos, float4) -------------------------
__global__ void sem_kernel(){
    __shared__ float wtab[4][17];
    int i = blockIdx.x;
    int tid = threadIdx.x;                 // 128
    if (tid < 68){
        int b = tid / 17, k = tid % 17;
        int j = i - 8 + k;
        float w = 0.f;
        if (j >= 0 && j < S_){
            int lo = min(i, j), de = abs(i - j);
            w = g_Dn[((size_t)(b*S_ + lo))*9 + de];
        }
        wtab[b][k] = w;
    }
    __syncthreads();

    int d = tid * 4;
    int kmin = (i < 8) ? (8 - i) : 0;
    int kmax = (i > S_-9) ? (S_-1-i) + 8 : 16;
    float acc = 0.f;
    #pragma unroll
    for (int b = 0; b < B_; b++){
        float4 Pi4 = *(const float4*)(g_P + ((size_t)(b*S_ + i))*D_ + d);
        for (int k = kmin; k <= kmax; k++){
            int j = i - 8 + k;
            float w = wtab[b][k];
            float4 Pj4 = *(const float4*)(g_P + ((size_t)(b*S_ + j))*D_ + d);
            acc += cos_poly((Pi4.x - Pj4.x)*w);
            acc += cos_poly((Pi4.y - Pj4.y)*w);
            acc += cos_poly((Pi4.z - Pj4.z)*w);
            acc += cos_poly((Pi4.w - Pj4.w)*w);
        }
    }
    float tot = blockReduceSum(acc);
    if (tid == 0){
        float counts = (float)(kmax - kmin + 1);
        g_sem[i] = tot / ((float)B_ * counts * (float)D_);
    }
}

// ------------------------- multi-scale coherence (poly sincos) -------------------------
__global__ void mscale_kernel(){
    __shared__ float Ps[80][33], Cs[80][33], Ss[80][33];
    __shared__ float red[256*5];
    int b = blockIdx.y, t0 = blockIdx.x*64;
    int tid = threadIdx.x;                 // 256
    int tl = tid & 63, dg = tid >> 6;
    float acc[5] = {0.f,0.f,0.f,0.f,0.f};
    for (int d0 = 0; d0 < D_; d0 += 32){
        for (int l = tid; l < 80*32; l += 256){
            int r = l >> 5, dc = l & 31;
            int gt = t0 + r;
            float p = 0.f, c = 0.f, s = 0.f;
            if (gt < S_){
                size_t idx = ((size_t)(b*S_ + gt))*D_ + d0 + dc;
                p = g_P[idx]; c = g_C[idx]; s = g_Sn[idx];
            }
            Ps[r][dc] = p; Cs[r][dc] = c; Ss[r][dc] = s;
        }
        __syncthreads();
        for (int dd = 0; dd < 8; dd++){
            int dc = dg*8 + dd;
            float sp = 0.f, sc = 0.f, ss = 0.f;
            #pragma unroll
            for (int r = 0; r < 16; r++){
                sp += Ps[tl+r][dc]; sc += Cs[tl+r][dc]; ss += Ss[tl+r][dc];
                if (r==0 || r==1 || r==3 || r==7 || r==15){
                    int sidx = (r==0)?0:(r==1)?1:(r==3)?2:(r==7)?3:4;
                    float inv = 1.f/(float)(r+1);
                    float wm = sp*inv;
                    acc[sidx] += cos_poly(wm)*(sc*inv) + sin_poly(wm)*(ss*inv);
                }
            }
        }
        __syncthreads();
    }
    #pragma unroll
    for (int s = 0; s < 5; s++) red[tid*5 + s] = acc[s];
    __syncthreads();
    if (dg == 0){
        int t = t0 + tl;
        #pragma unroll
        for (int s5 = 0; s5 < 5; s5++){
            float v = red[tl*5+s5] + red[(tl+64)*5+s5]
                    + red[(tl+128)*5+s5] + red[(tl+192)*5+s5];
            int sv = 1 << s5;
            g_msc[((size_t)(b*S_ + t))*5 + s5] = (t + sv <= S_) ? v*(1.f/D_) : 0.f;
        }
    }
}

// ------------------------- fuse epilogue + LN1 + GELU -------------------------
__global__ void fuse_ln1_kernel(const float* __restrict__ g1, const float* __restrict__ b1){
    int n = blockIdx.x;
    int tid = threadIdx.x;                 // 128
    int t = n & (S_-1);
    float sem = g_sem[t];
    float m0 = g_msc[(size_t)n*5+0], m1 = g_msc[(size_t)n*5+1], m2 = g_msc[(size_t)n*5+2];
    float m3 = g_msc[(size_t)n*5+3], m4 = g_msc[(size_t)n*5+4];
    float v[4]; float s = 0.f;
    #pragma unroll
    for (int j = 0; j < 4; j++){
        int c = tid + 128*j;
        float x = g_y[(size_t)n*D_ + c] + g_biasc[c] + sem*g_wsem[c]
                + m0*g_Ws5[c] + m1*g_Ws5[D_+c] + m2*g_Ws5[2*D_+c]
                + m3*g_Ws5[3*D_+c] + m4*g_Ws5[4*D_+c];
        v[j] = x; s += x;
    }
    float mean = blockReduceSum(s) * (1.f/D_);
    float q = 0.f;
    #pragma unroll
    for (int j = 0; j < 4; j++){ float d = v[j]-mean; q += d*d; }
    float var = blockReduceSum(q) * (1.f/D_);
    float rstd = rsqrtf(var + 1e-5f);
    #pragma unroll
    for (int j = 0; j < 4; j++){
        int c = tid + 128*j;
        float h = (v[j]-mean)*rstd*g1[c] + b1[c];
        g_x[(size_t)n*D_ + c] = gelu_exact(h);
    }
}

// ------------------------- plain LayerNorm -------------------------
__global__ void ln_plain_kernel(const float* __restrict__ src, const float* __restrict__ g,
                                const float* __restrict__ b, float* __restrict__ dst){
    int n = blockIdx.x; int tid = threadIdx.x;      // 128
    const float* r = src + (size_t)n*D_;
    float v[4]; float s = 0.f;
    #pragma unroll
    for (int j = 0; j < 4; j++){ v[j] = r[tid + 128*j]; s += v[j]; }
    float mean = blockReduceSum(s) * (1.f/D_);
    float q = 0.f;
    #pragma unroll
    for (int j = 0; j < 4; j++){ float d = v[j]-mean; q += d*d; }
    float var = blockReduceSum(q) * (1.f/D_);
    float rstd = rsqrtf(var + 1e-5f);
    #pragma unroll
    for (int j = 0; j < 4; j++){
        int c = tid + 128*j;
        dst[(size_t)n*D_ + c] = (v[j]-mean)*rstd*g[c] + b[c];
    }
}

// ------------------------- fused residual + LayerNorm -------------------------
__global__ void resid_ln_kernel(const float* __restrict__ h, const float* __restrict__ g,
                                const float* __restrict__ b, float* __restrict__ dst){
    int n = blockIdx.x; int tid = threadIdx.x;      // 128
    float v[4]; float s = 0.f;
    #pragma unroll
    for (int j = 0; j < 4; j++){
        int c = tid + 128*j;
        float x = g_x[(size_t)n*D_ + c] + 0.1f*gelu_exact(h[(size_t)n*D_ + c]);
        g_x[(size_t)n*D_ + c] = x;
        v[j] = x; s += x;
    }
    float mean = blockReduceSum(s) * (1.f/D_);
    float q = 0.f;
    #pragma unroll
    for (int j = 0; j < 4; j++){ float d = v[j]-mean; q += d*d; }
    float var = blockReduceSum(q) * (1.f/D_);
    float rstd = rsqrtf(var + 1e-5f);
    #pragma unroll
    for (int j = 0; j < 4; j++){
        int c = tid + 128*j;
        dst[(size_t)n*D_ + c] = (v[j]-mean)*rstd*g[c] + b[c];
    }
}

// ------------------------- launch -------------------------
extern "C" void kernel_launch(void* const* d_in, const int* in_sizes, int n_in,
                              void* d_out, int out_size){
    (void)in_sizes; (void)n_in; (void)out_size;
    const float* emb     = (const float*)d_in[0];
    const int*   tok     = (const int*)  d_in[1];
    const float* mask    = (const float*)d_in[2];
    const float* tsm     = (const float*)d_in[3];
    const float* W_scale = (const float*)d_in[4];
    const float* b_scale = (const float*)d_in[5];
    const float* W_sem   = (const float*)d_in[6];
    const float* b_sem   = (const float*)d_in[7];
    const float* W_ctx   = (const float*)d_in[8];
    const float* b_ctx   = (const float*)d_in[9];
    const float* W_fuse  = (const float*)d_in[10];
    const float* b_fuse  = (const float*)d_in[11];
    const float* ln1g = (const float*)d_in[12]; const float* ln1b = (const float*)d_in[13];
    const float* ln2g = (const float*)d_in[14]; const float* ln2b = (const float*)d_in[15];
    const float* ln3g = (const float*)d_in[16]; const float* ln3b = (const float*)d_in[17];
    const float* We[3] = {(const float*)d_in[18], (const float*)d_in[20], (const float*)d_in[22]};
    const float* be[3] = {(const float*)d_in[19], (const float*)d_in[21], (const float*)d_in[23]};
    float* out = (float*)d_out;

    float *pWbig, *pFeat, *pY, *pX, *pT, *pH;
    cudaGetSymbolAddress((void**)&pWbig, g_Wbig);
    cudaGetSymbolAddress((void**)&pFeat, g_feat);
    cudaGetSymbolAddress((void**)&pY,    g_y);
    cudaGetSymbolAddress((void**)&pX,    g_x);
    cudaGetSymbolAddress((void**)&pT,    g_t);
    cudaGetSymbolAddress((void**)&pH,    g_h);

    // features first (reordered so the ncu -s 5 slot lands on band/bandnorm)
    phase_kernel  <<<NTOT*D_/256, 256>>>(emb);
    cmean_part_kernel <<<dim3(64, B_), 256>>>(emb, mask);
    cmean_final_kernel<<<B_, 512>>>();
    ctxfeat_kernel<<<NTOT*D_/256, 256>>>(emb);
    foldw_kernel<<<7, 512>>>(W_scale, W_sem, b_scale, b_sem, b_ctx, b_fuse, W_fuse);

    // banded similarity + sem
    band_kernel    <<<dim3(S_/16, B_), 192>>>(tsm, tok);
    bandnorm_kernel<<<NTOT/256, 256>>>();
    sem_kernel     <<<S_, 128>>>();

    // multi-scale coherence
    mscale_kernel<<<dim3(S_/64, B_), 256>>>();

    // weight-fold GEMM for Wbig, then fused projection
    sgemm_kernel<<<dim3(4,4), 256>>>(W_ctx, W_fuse + (size_t)2*D_*D_, nullptr, pWbig,
                                     D_, D_, D_);
    cudaMemcpyAsync(pWbig + D_*D_, W_fuse + (size_t)3*D_*D_,
                    (size_t)D_*D_*sizeof(float), cudaMemcpyDeviceToDevice);
    sgemm_kernel<<<dim3(4,32), 256>>>(pFeat, pWbig, nullptr, pY, NTOT, D_, 2*D_);
    fuse_ln1_kernel<<<NTOT, 128>>>(ln1g, ln1b);

    // residual blocks (resid fused into following LN)
    ln_plain_kernel<<<NTOT, 128>>>(pX, ln2g, ln2b, pT);
    for (int l = 0; l < 3; l++){
        sgemm_kernel<<<dim3(4,32), 256>>>(pT, We[l], be[l], pH, NTOT, D_, D_);
        if (l < 2) resid_ln_kernel<<<NTOT, 128>>>(pH, ln2g, ln2b, pT);
        else       resid_ln_kernel<<<NTOT, 128>>>(pH, ln3g, ln3b, out);
    }
}